// round 8
// baseline (speedup 1.0000x reference)
#include <cuda_runtime.h>
#include <cstdint>

#define PL1 20
#define PR1 70
#define PL2 120
#define PR2 170
#define NFACT 10
#define TT 200
#define NTRIALS 256
#define NCONFIGS 128
#define TW 50
#define NOFF (2 * NFACT)

#define N_WARP_BLOCKS (NTRIALS * NOFF)            // 5120
#define BCAST_ROWS (NFACT * 100)                  // 1000
#define BCAST_PARTS 4                             // 8192 floats per part
#define N_BCAST_BLOCKS (BCAST_ROWS * BCAST_PARTS) // 4000

__device__ __forceinline__ float softplus_f(float x) {
    // jax.nn.softplus: max(x,0) + log1p(exp(-|x|))
    return fmaxf(x, 0.0f) + log1pf(expf(-fabsf(x)));
}

// ---------------------------------------------------------------------------
// One fused kernel, one wave. blockIdx.x < 5120 -> warped-window role,
// else -> broadcast-fill role. 64 threads per block.
// ---------------------------------------------------------------------------
__global__ void __launch_bounds__(64) fused_kernel(
    const float* __restrict__ beta,        // (10, 200)
    const float* __restrict__ trial_off,   // (256, 128, 20)
    const float* __restrict__ cfg_off,     // (128, 20)
    const float* __restrict__ time,        // (200,)
    float* __restrict__ out) {             // (10, 200, 256, 128)

    const int bid = blockIdx.x;
    const int tid = threadIdx.x;

    if (bid >= N_WARP_BLOCKS) {
        // ------------------- broadcast role -------------------
        int b    = bid - N_WARP_BLOCKS;
        int row  = b >> 2;                 // 0..999
        int part = b & 3;
        int f    = row / 100;
        int r    = row % 100;
        int tt;
        if (r < PL1)                        tt = r;                           // [0,20)
        else if (r < PL1 + (PL2 - PR1))     tt = r + (PR1 - PL1);             // [70,120)
        else                                tt = r + (PR1 - PL1) + (PR2 - PL2); // [170,200)

        float v = softplus_f(beta[f * TT + tt]);
        float4 v4 = make_float4(v, v, v, v);
        float4* base = reinterpret_cast<float4*>(
            out + ((size_t)f * TT + tt) * (NTRIALS * NCONFIGS)) + part * 2048;
#pragma unroll 4
        for (int i = tid; i < 2048; i += 64)
            __stcs(base + i, v4);
        return;
    }

    // ------------------- warped-window role -------------------
    const int j    = bid / NTRIALS;        // 0..19
    const int t    = bid % NTRIALS;
    const int side = j / NFACT;
    const int f    = j % NFACT;
    const int baseT = side ? PL2 : PL1;

    __shared__ float s_f[TW + 2];          // F[i] = softplus(beta[f, baseT+i]), i=0..51
    __shared__ float s_A[TW + 1];          // A[i] = F[i] - i*(F[i+1]-F[i])
    __shared__ float s_B[TW + 1];          // B[i] = F[i+1]-F[i]
    __shared__ float s_pk;

    if (tid < TW + 2)
        s_f[tid] = softplus_f(beta[f * TT + baseT + tid]);
    __syncthreads();

    if (tid <= TW) {
        float d = s_f[tid + 1] - s_f[tid];
        s_B[tid] = d;
        s_A[tid] = fmaf(-(float)tid, d, s_f[tid]);
    }
    // first-max argmax over s_f[0..49] (same tie rule as jnp.argmax)
    if (tid < 32) {
        float v = (tid < TW) ? s_f[tid] : -3.402823466e+38f;
        int   idx = tid;
        int   i2  = tid + 32;
        if (i2 < TW) {
            float v2 = s_f[i2];
            if (v2 > v) { v = v2; idx = i2; }
        }
#pragma unroll
        for (int d = 16; d; d >>= 1) {
            float ov = __shfl_down_sync(0xffffffffu, v, d);
            int   oi = __shfl_down_sync(0xffffffffu, idx, d);
            if (ov > v || (ov == v && oi < idx)) { v = ov; idx = oi; }
        }
        if (tid == 0) s_pk = time[baseT + idx];
    }
    __syncthreads();

    const int lane = tid & 31;
    // Register-resident line-parameter table (shfl-indexed, no smem gather).
    // Entry i (0..50): lo half from lane i, hi half (i>=32) from lane i-32.
    const float A0 = s_A[lane];
    const float B0 = s_B[lane];
    const float A1 = (lane + 32 <= TW) ? s_A[lane + 32] : 0.0f;
    const float B1 = (lane + 32 <= TW) ? s_B[lane + 32] : 0.0f;

    const float tl = time[baseT];
    const float tr = time[baseT + TW];
    const float dt = time[1] - time[0];
    const float inv_dt = 1.0f / dt;
    const float pk = s_pk;
    const float nbT = -(float)baseT;

    const int w  = tid >> 5;               // 0 or 1
    const int c0 = lane * 4;

    float lsp[4], lslope[4], rslope[4];
#pragma unroll
    for (int q = 0; q < 4; ++q) {
        int c = c0 + q;
        float off = trial_off[((size_t)t * NCONFIGS + c) * NOFF + j]
                  + cfg_off[c * NOFF + j];
        float sn = pk + off;
        if (sn <= tl) sn = tl + dt;
        if (sn >= tr) sn = tr - dt;
        lsp[q]    = sn - tl;
        lslope[q] = (pk - tl) / lsp[q];
        rslope[q] = (pk - tr) / (sn - tr);
    }

    const int twlo = w * (TW / 2);
    const int twhi = twlo + (TW / 2);
    for (int tw = twlo; tw < twhi; ++tw) {
        float lst = (float)tw * dt;
        float4 v;
        float* vp = &v.x;
#pragma unroll
        for (int q = 0; q < 4; ++q) {
            float wt  = (lst < lsp[q]) ? fmaf(lst, lslope[q], tl)
                                       : fmaf(lst - lsp[q], rslope[q], pk);
            float wip = fmaf(wt, inv_dt, nbT);            // window coords
            wip = fminf(fmaxf(wip, 0.0f), (float)TW);     // clamp -> index safe
            int   i  = (int)wip;                          // floor (wip >= 0)
            // shfl uses srcLane & 31, so i and i-32 resolve identically
            float a0 = __shfl_sync(0xffffffffu, A0, i);
            float a1 = __shfl_sync(0xffffffffu, A1, i);
            float b0 = __shfl_sync(0xffffffffu, B0, i);
            float b1 = __shfl_sync(0xffffffffu, B1, i);
            bool  hi = i >= 32;
            float Aq = hi ? a1 : a0;
            float Bq = hi ? b1 : b0;
            vp[q] = fmaf(wip, Bq, Aq);
        }
        size_t oidx = (((size_t)f * TT + baseT + tw) * NTRIALS + t) * NCONFIGS + c0;
        __stcs(reinterpret_cast<float4*>(out + oidx), v);
    }
}

// ---------------------------------------------------------------------------
extern "C" void kernel_launch(void* const* d_in, const int* in_sizes, int n_in,
                              void* d_out, int out_size) {
    const float* beta  = (const float*)d_in[0];   // (10, 200)
    const float* trial = (const float*)d_in[1];   // (1, 256, 128, 20)
    const float* cfg   = (const float*)d_in[2];   // (1, 128, 20)
    const float* time  = (const float*)d_in[3];   // (200,)
    float* out = (float*)d_out;                   // (10,200,1,1,256,128)

    fused_kernel<<<N_WARP_BLOCKS + N_BCAST_BLOCKS, 64>>>(beta, trial, cfg, time, out);
}

// round 9
// speedup vs baseline: 1.0242x; 1.0242x over previous
#include <cuda_runtime.h>
#include <cstdint>

#define PL1 20
#define PR1 70
#define PL2 120
#define PR2 170
#define NFACT 10
#define TT 200
#define NTRIALS 256
#define NCONFIGS 128
#define TW 50
#define NOFF (2 * NFACT)

// 128-thread blocks: warp-role block = (j, trial-pair); 4 warps = 2 trials x 2 tw-halves
#define N_WARP_BLOCKS ((NTRIALS / 2) * NOFF)      // 2560
#define BCAST_ROWS (NFACT * 100)                  // 1000
#define BCAST_PARTS 2                             // 4096 float4 per part
#define N_BCAST_BLOCKS (BCAST_ROWS * BCAST_PARTS) // 2000

__device__ __forceinline__ float softplus_f(float x) {
    // jax.nn.softplus: max(x,0) + log1p(exp(-|x|))
    return fmaxf(x, 0.0f) + log1pf(expf(-fabsf(x)));
}

// ---------------------------------------------------------------------------
__global__ void __launch_bounds__(128) fused_kernel(
    const float* __restrict__ beta,        // (10, 200)
    const float* __restrict__ trial_off,   // (256, 128, 20)
    const float* __restrict__ cfg_off,     // (128, 20)
    const float* __restrict__ time,        // (200,)
    float* __restrict__ out) {             // (10, 200, 256, 128)

    const int bid = blockIdx.x;
    const int tid = threadIdx.x;

    if (bid >= N_WARP_BLOCKS) {
        // ------------------- broadcast role -------------------
        int b    = bid - N_WARP_BLOCKS;
        int row  = b >> 1;                 // 0..999
        int part = b & 1;
        int f    = row / 100;
        int r    = row % 100;
        int tt;
        if (r < PL1)                        tt = r;                           // [0,20)
        else if (r < PL1 + (PL2 - PR1))     tt = r + (PR1 - PL1);             // [70,120)
        else                                tt = r + (PR1 - PL1) + (PR2 - PL2); // [170,200)

        float v = softplus_f(beta[f * TT + tt]);
        float4 v4 = make_float4(v, v, v, v);
        float4* base = reinterpret_cast<float4*>(
            out + ((size_t)f * TT + tt) * (NTRIALS * NCONFIGS)) + part * 4096;
#pragma unroll 4
        for (int i = tid; i < 4096; i += 128)
            __stcs(base + i, v4);
        return;
    }

    // ------------------- warped-window role -------------------
    const int j    = bid / (NTRIALS / 2);  // 0..19
    const int tp   = bid % (NTRIALS / 2);  // trial pair
    const int side = j / NFACT;
    const int f    = j % NFACT;
    const int baseT = side ? PL2 : PL1;

    __shared__ float s_f[TW + 2];              // F[i], i=0..51
    __shared__ float s_Ac[TW + 1];             // compact A[i] = F[i] - i*(F[i+1]-F[i])
    __shared__ float s_Bc[TW + 1];             // compact B[i] = F[i+1]-F[i]
    __shared__ float s_A[(TW + 1) * 32];       // lane-privatized: A at [i*32+lane]
    __shared__ float s_B[(TW + 1) * 32];       // lane-privatized: B at [i*32+lane]
    __shared__ float s_pk;

    if (tid < TW + 2)
        s_f[tid] = softplus_f(beta[f * TT + baseT + tid]);
    __syncthreads();

    if (tid <= TW) {
        float d = s_f[tid + 1] - s_f[tid];
        s_Bc[tid] = d;
        s_Ac[tid] = fmaf(-(float)tid, d, s_f[tid]);
    }
    // first-max argmax over s_f[0..49] (same tie rule as jnp.argmax)
    if (tid < 32) {
        float v = (tid < TW) ? s_f[tid] : -3.402823466e+38f;
        int   idx = tid;
        int   i2  = tid + 32;
        if (i2 < TW) {
            float v2 = s_f[i2];
            if (v2 > v) { v = v2; idx = i2; }
        }
#pragma unroll
        for (int d = 16; d; d >>= 1) {
            float ov = __shfl_down_sync(0xffffffffu, v, d);
            int   oi = __shfl_down_sync(0xffffffffu, idx, d);
            if (ov > v || (ov == v && oi < idx)) { v = ov; idx = oi; }
        }
        if (tid == 0) s_pk = time[baseT + idx];
    }
    __syncthreads();

    const int lane = tid & 31;
    const int w    = tid >> 5;             // 0..3

    // Fill lane-privatized tables: bank(lane) always -> conflict-free fill & gather
    for (int i = w; i <= TW; i += 4) {
        s_A[i * 32 + lane] = s_Ac[i];      // LDS broadcast + STS bank=lane
        s_B[i * 32 + lane] = s_Bc[i];
    }
    __syncthreads();

    const float tl = time[baseT];
    const float tr = time[baseT + TW];
    const float dt = time[1] - time[0];
    const float inv_dt = 1.0f / dt;
    const float pk = s_pk;
    const float nbT = -(float)baseT;

    const int t  = tp * 2 + (w >> 1);      // this warp's trial
    const int c0 = lane * 4;

    float lsp[4], lslope[4], rslope[4];
#pragma unroll
    for (int q = 0; q < 4; ++q) {
        int c = c0 + q;
        float off = trial_off[((size_t)t * NCONFIGS + c) * NOFF + j]
                  + cfg_off[c * NOFF + j];
        float sn = pk + off;
        if (sn <= tl) sn = tl + dt;
        if (sn >= tr) sn = tr - dt;
        lsp[q]    = sn - tl;
        lslope[q] = (pk - tl) / lsp[q];
        rslope[q] = (pk - tr) / (sn - tr);
    }

    const int twlo = (w & 1) * (TW / 2);
    const int twhi = twlo + (TW / 2);
    for (int tw = twlo; tw < twhi; ++tw) {
        float lst = (float)tw * dt;
        float4 v;
        float* vp = &v.x;
#pragma unroll
        for (int q = 0; q < 4; ++q) {
            float wt  = (lst < lsp[q]) ? fmaf(lst, lslope[q], tl)
                                       : fmaf(lst - lsp[q], rslope[q], pk);
            float wip = fmaf(wt, inv_dt, nbT);            // window coords [0,50]
            wip = fminf(fmaxf(wip, 0.0f), (float)TW);
            int   i  = (int)wip;                          // floor (wip >= 0)
            float Aq = s_A[i * 32 + lane];                // bank=lane, conflict-free
            float Bq = s_B[i * 32 + lane];
            vp[q] = fmaf(wip, Bq, Aq);
        }
        size_t oidx = (((size_t)f * TT + baseT + tw) * NTRIALS + t) * NCONFIGS + c0;
        __stcs(reinterpret_cast<float4*>(out + oidx), v);
    }
}

// ---------------------------------------------------------------------------
extern "C" void kernel_launch(void* const* d_in, const int* in_sizes, int n_in,
                              void* d_out, int out_size) {
    const float* beta  = (const float*)d_in[0];   // (10, 200)
    const float* trial = (const float*)d_in[1];   // (1, 256, 128, 20)
    const float* cfg   = (const float*)d_in[2];   // (1, 128, 20)
    const float* time  = (const float*)d_in[3];   // (200,)
    float* out = (float*)d_out;                   // (10,200,1,1,256,128)

    fused_kernel<<<N_WARP_BLOCKS + N_BCAST_BLOCKS, 128>>>(beta, trial, cfg, time, out);
}